// round 14
// baseline (speedup 1.0000x reference)
#include <cuda_runtime.h>
#include <cuda_fp16.h>
#include <cstdint>

#define NN 50000
#define NE 600000
#define HIDD 128
#define AS2 136                      // padded row stride in halves: conflict-free
// dynamic smem: W1 | W2 | A (each 128*AS2 fp16) + stat floats
#define SMEM_BYTES (3 * 128 * AS2 * 2 + 2048)
#define NB ((NN + 127) / 128)        // 391 tiles
#define NSB ((NN + 255) / 256)       // scan blocks (196)
#define PGRID 296                    // persistent grid: 2 CTAs/SM

#define ST_AGG (1 << 30)
#define ST_INC (2 << 30)
#define VALMASK 0x3FFFFFFF

// ---------------- device scratch (static, no runtime alloc) ----------------
__device__ __align__(16) __half g_h0[(size_t)NN * HIDD];   // fp16 x
__device__ __align__(16) __half g_h1[(size_t)NN * HIDD];   // fp16 activations
__device__ __align__(16) __half g_h2[(size_t)NN * HIDD];
// padded by 128 rows so tile prefetch past NN stays in-bounds
__device__ __align__(16) __half g_agg[(size_t)(NN + 128) * HIDD];
__device__ int   g_deg[NN];
__device__ int   g_rowptr[NN + 1];
__device__ int   g_cursor[NN];
__device__ __align__(16) int g_esrc[NE + 8];
__device__ int   g_lb[NSB];
__device__ int   g_done;
__device__ int   g_sync;
__device__ float g_tap[4 * HIDD];

// ---------------- helpers ----------------
__device__ __forceinline__ void mma16(float c[4], unsigned a0, unsigned a1, unsigned a2,
                                      unsigned a3, unsigned b0, unsigned b1) {
    asm volatile(
        "mma.sync.aligned.m16n8k16.row.col.f32.f16.f16.f32 "
        "{%0,%1,%2,%3},{%4,%5,%6,%7},{%8,%9},{%0,%1,%2,%3};"
        : "+f"(c[0]), "+f"(c[1]), "+f"(c[2]), "+f"(c[3])
        : "r"(a0), "r"(a1), "r"(a2), "r"(a3), "r"(b0), "r"(b1));
}

__device__ __forceinline__ void ldsm4(unsigned r[4], uint32_t addr) {
    asm volatile("ldmatrix.sync.aligned.m8n8.x4.shared.b16 {%0,%1,%2,%3}, [%4];"
                 : "=r"(r[0]), "=r"(r[1]), "=r"(r[2]), "=r"(r[3]) : "r"(addr));
}

__device__ __forceinline__ uint32_t smem_u32(const void* p) {
    uint32_t a;
    asm("{ .reg .u64 t; cvta.to.shared.u64 t, %1; cvt.u32.u64 %0, t; }" : "=r"(a) : "l"(p));
    return a;
}

__device__ __forceinline__ void cp_async8(uint32_t dst, const void* src) {
    asm volatile("cp.async.ca.shared.global [%0], [%1], 8;" :: "r"(dst), "l"(src));
}
#define CP_COMMIT() asm volatile("cp.async.commit_group;" ::: "memory")
#define CP_WAIT0()  asm volatile("cp.async.wait_group 0;" ::: "memory")

// accumulate a single fp16 uint4 (8 halves) into 8 fp32
__device__ __forceinline__ void acc8(float f[8], uint4 v) {
    float2 a0 = __half22float2(*(__half2*)&v.x);
    float2 a1 = __half22float2(*(__half2*)&v.y);
    float2 a2 = __half22float2(*(__half2*)&v.z);
    float2 a3 = __half22float2(*(__half2*)&v.w);
    f[0] += a0.x; f[1] += a0.y; f[2] += a1.x; f[3] += a1.y;
    f[4] += a2.x; f[5] += a2.y; f[6] += a3.x; f[7] += a3.y;
}

// fp16 tree of 4 uint4s, then fp32 accumulate
__device__ __forceinline__ void tree4_8(float f[8], uint4 v0, uint4 v1, uint4 v2, uint4 v3) {
    __half2 s0 = __hadd2(__hadd2(*(__half2*)&v0.x, *(__half2*)&v1.x),
                         __hadd2(*(__half2*)&v2.x, *(__half2*)&v3.x));
    __half2 s1 = __hadd2(__hadd2(*(__half2*)&v0.y, *(__half2*)&v1.y),
                         __hadd2(*(__half2*)&v2.y, *(__half2*)&v3.y));
    __half2 s2 = __hadd2(__hadd2(*(__half2*)&v0.z, *(__half2*)&v1.z),
                         __hadd2(*(__half2*)&v2.z, *(__half2*)&v3.z));
    __half2 s3 = __hadd2(__hadd2(*(__half2*)&v0.w, *(__half2*)&v1.w),
                         __hadd2(*(__half2*)&v2.w, *(__half2*)&v3.w));
    float2 a0 = __half22float2(s0), a1 = __half22float2(s1);
    float2 a2 = __half22float2(s2), a3 = __half22float2(s3);
    f[0] += a0.x; f[1] += a0.y; f[2] += a1.x; f[3] += a1.y;
    f[4] += a2.x; f[5] += a2.y; f[6] += a3.x; f[7] += a3.y;
}

// ---------------- CSR build ----------------
__global__ void hist_k(const int* __restrict__ dst, const float* __restrict__ x) {
    int i = blockIdx.x * blockDim.x + threadIdx.x;
    if (i == 0) { g_done = 0; g_sync = 0; }
    if (i < NSB) g_lb[i] = 0;
    if (i < 4 * HIDD) g_tap[i] = 0.f;
    if (i < NE) atomicAdd(&g_deg[dst[i]], 1);
    const float2* x2 = (const float2*)x;
    __half2* h2 = (__half2*)g_h0;
    const int total = NN * HIDD / 2;
    for (int j = i; j < total; j += NE) {
        float2 v = x2[j];
        h2[j] = __floats2half2_rn(v.x, v.y);
    }
}

// fused: decoupled-lookback scan of g_deg -> grid barrier -> scatter edges
__global__ __launch_bounds__(256) void scan_scatter_k(const int* __restrict__ src,
                                                      const int* __restrict__ dst) {
    __shared__ int warpsum[8];
    __shared__ int s_prefix;
    const int b = blockIdx.x, t = threadIdx.x;
    const int lane = t & 31, wid = t >> 5;
    const int i = b * 256 + t;
    int d = (i < NN) ? g_deg[i] : 0;

    int v = d;
#pragma unroll
    for (int o = 1; o < 32; o <<= 1) {
        int u = __shfl_up_sync(0xffffffffu, v, o);
        if (lane >= o) v += u;
    }
    if (lane == 31) warpsum[wid] = v;
    __syncthreads();
    if (t < 8) {
        int wv = warpsum[t];
#pragma unroll
        for (int o = 1; o < 8; o <<= 1) {
            int u = __shfl_up_sync(0xffu, wv, o);
            if (t >= o) wv += u;
        }
        warpsum[t] = wv;
    }
    __syncthreads();
    const int incl = v + (wid ? warpsum[wid - 1] : 0);
    const int total = warpsum[7];

    if (t == 0) {
        if (b == 0) atomicExch(&g_lb[0], ST_INC | total);
        else        atomicExch(&g_lb[b], ST_AGG | total);
    }

    if (wid == 0) {
        int prefix = 0;
        if (b > 0) {
            int idx = b - 1;
            while (true) {
                int j = idx - lane;
                int w = (j >= 0) ? atomicAdd(&g_lb[j], 0) : (ST_INC | 0);
                if (!__all_sync(0xffffffffu, w != 0)) continue;
                unsigned incmask = __ballot_sync(0xffffffffu, (w & ST_INC) != 0);
                if (incmask) {
                    int first = __ffs(incmask) - 1;
                    int contrib = (lane <= first) ? (w & VALMASK) : 0;
#pragma unroll
                    for (int o = 16; o; o >>= 1) contrib += __shfl_xor_sync(0xffffffffu, contrib, o);
                    prefix += contrib;
                    break;
                } else {
                    int contrib = w & VALMASK;
#pragma unroll
                    for (int o = 16; o; o >>= 1) contrib += __shfl_xor_sync(0xffffffffu, contrib, o);
                    prefix += contrib;
                    idx -= 32;
                }
            }
            if (lane == 0) atomicExch(&g_lb[b], ST_INC | (prefix + total));
        }
        if (lane == 0) s_prefix = prefix;
    }
    __syncthreads();
    int rp = s_prefix + incl - d;
    if (i < NN) { g_rowptr[i] = rp; g_cursor[i] = rp; }
    if (i == NN - 1) g_rowptr[NN] = NE;

    // ---- grid barrier: all cursors published before any scatter ----
    __threadfence();
    __syncthreads();
    if (t == 0) {
        atomicAdd(&g_sync, 1);
        while (atomicAdd(&g_sync, 0) < NSB) { }
    }
    __syncthreads();

    // ---- scatter: grid-stride over edges ----
    for (int e = b * 256 + t; e < NE; e += NSB * 256) {
        int dd = dst[e];
        int pos = atomicAdd(&g_cursor[dd], 1);
        g_esrc[pos] = src[e];
    }
}

// ---------------- aggregation: 2 nodes per warp, uint4 rows, fp16 trees ----------------
__global__ __launch_bounds__(256) void agg_k(const __half* __restrict__ Xin) {
    const int warpId = (blockIdx.x * blockDim.x + threadIdx.x) >> 5;
    const int lane = threadIdx.x & 31;
    const int n = warpId * 2 + (lane >> 4);    // half-warp per node
    const int c = lane & 15;                   // 16 uint4 per 128-half row
    if (n >= NN) return;
    const uint4* X4 = (const uint4*)Xin;

    float f[8];
    {   // self term (eps=0 GIN)
        uint4 sv = X4[(size_t)n * 16 + c];
        float2 a0 = __half22float2(*(__half2*)&sv.x);
        float2 a1 = __half22float2(*(__half2*)&sv.y);
        float2 a2 = __half22float2(*(__half2*)&sv.z);
        float2 a3 = __half22float2(*(__half2*)&sv.w);
        f[0] = a0.x; f[1] = a0.y; f[2] = a1.x; f[3] = a1.y;
        f[4] = a2.x; f[5] = a2.y; f[6] = a3.x; f[7] = a3.y;
    }

    int e = g_rowptr[n];
    const int e1 = g_rowptr[n + 1];
    for (; e + 4 <= e1; e += 4) {
        int s0 = g_esrc[e],     s1 = g_esrc[e + 1];
        int s2 = g_esrc[e + 2], s3 = g_esrc[e + 3];
        uint4 v0 = X4[(size_t)s0 * 16 + c];
        uint4 v1 = X4[(size_t)s1 * 16 + c];
        uint4 v2 = X4[(size_t)s2 * 16 + c];
        uint4 v3 = X4[(size_t)s3 * 16 + c];
        tree4_8(f, v0, v1, v2, v3);
    }
    for (; e < e1; e++)
        acc8(f, X4[(size_t)g_esrc[e] * 16 + c]);

    __half2 o0 = __floats2half2_rn(f[0], f[1]);
    __half2 o1 = __floats2half2_rn(f[2], f[3]);
    __half2 o2 = __floats2half2_rn(f[4], f[5]);
    __half2 o3 = __floats2half2_rn(f[6], f[7]);
    uint4 st;
    st.x = *(unsigned*)&o0; st.y = *(unsigned*)&o1;
    st.z = *(unsigned*)&o2; st.w = *(unsigned*)&o3;
    ((uint4*)g_agg)[(size_t)n * 16 + c] = st;
}

// ---------------- persistent GIN MLP layer: 256 thr, 2 CTAs/SM, m32n64 warps ----------------
__global__ __launch_bounds__(256, 2) void gin_layer(
    __half* __restrict__ Xout, int tap_off, int do_readout,
    const float* __restrict__ W1, const float* __restrict__ b1,
    const float* __restrict__ gam, const float* __restrict__ bet,
    const float* __restrict__ mu, const float* __restrict__ var,
    const float* __restrict__ W2, const float* __restrict__ b2,
    const float* __restrict__ Wll, const float* __restrict__ bll,
    float* __restrict__ out)
{
    extern __shared__ __half smh[];
    __half* sW1 = smh;                      // 128 x AS2 fp16 (BN-folded W1)
    __half* sW2 = smh + 128 * AS2;          // 128 x AS2 fp16 W2
    __half* sA  = smh + 2 * 128 * AS2;      // 128 x AS2 fp16 (A, then H1)
    float* sB1    = (float*)(smh + 3 * 128 * AS2);
    float* sB2    = sB1 + 128;
    float* sTap   = sB2 + 128;
    float* sScale = sTap + 128;

    float* tap = g_tap + tap_off;

    const int tid = threadIdx.x;
    const int w = tid >> 5, lane = tid & 31;

    const uint2* A2 = (const uint2*)g_agg;
    const uint32_t aBase = smem_u32(sA);

    // prefetch first tile into sA FIRST — overlaps the weight fold below
    {
        int tile = blockIdx.x;
        if (tile < NB) {
            for (int idx = tid; idx < 4096; idx += 256) {
                int r = idx >> 5, c4 = idx & 31;
                cp_async8(aBase + (r * AS2 + c4 * 4) * 2,
                          &A2[(size_t)(tile * 128 + r) * 32 + c4]);
            }
            CP_COMMIT();
        }
    }

    if (tid < 128) {
        float sc = gam[tid] * rsqrtf(var[tid] + 1e-5f);
        sScale[tid] = sc;
        sTap[tid] = 0.f;
        sB2[tid] = b2[tid];
        sB1[tid] = (b1[tid] - mu[tid]) * sc + bet[tid];
    }
    __syncthreads();   // sScale visible for weight fold

    // --- load both weight matrices once (float4 -> fp16) ---
    const float4* W14 = (const float4*)W1;
    const float4* W24 = (const float4*)W2;
    for (int idx = tid; idx < 4096; idx += 256) {
        int c = idx >> 5, k4 = (idx & 31) * 4;
        float s = sScale[c];
        float4 v1 = W14[idx];
        __half2 a0 = __floats2half2_rn(v1.x * s, v1.y * s);
        __half2 a1 = __floats2half2_rn(v1.z * s, v1.w * s);
        uint2 u1; u1.x = *(unsigned*)&a0; u1.y = *(unsigned*)&a1;
        *(uint2*)&sW1[c * AS2 + k4] = u1;
        float4 v2 = W24[idx];
        __half2 b0h = __floats2half2_rn(v2.x, v2.y);
        __half2 b1h = __floats2half2_rn(v2.z, v2.w);
        uint2 u2; u2.x = *(unsigned*)&b0h; u2.y = *(unsigned*)&b1h;
        *(uint2*)&sW2[c * AS2 + k4] = u2;
    }

    // warp tiling: 8 warps = 4 row-tiles (m32) x 2 col-strips (n64)
    const int wr = w & 3, wc = w >> 2;
    const int rb = wr * 32, cb = wc * 64;
    const int gq = lane >> 2, q = lane & 3;

    // ldmatrix lane address components
    const int lg = lane >> 3, lr = lane & 7;
    const uint32_t aOff0 = ((rb + (lg & 1) * 8 + lr) * AS2 + ((lg >> 1) * 8)) * 2;
    const uint32_t aOff1 = aOff0 + 16 * AS2 * 2;
    const uint32_t aAddr0 = aBase + aOff0;
    const uint32_t aAddr1 = aBase + aOff1;
    const uint32_t bOffC = (((lg >> 1) * 8 + lr) * AS2 + ((lg & 1) * 8)) * 2;
    const uint32_t bStep = 16 * AS2 * 2;
    const uint32_t b1A = smem_u32(sW1) + (cb * AS2) * 2 + bOffC;
    const uint32_t b2A = smem_u32(sW2) + (cb * AS2) * 2 + bOffC;

    float tS0[8], tS1[8];
#pragma unroll
    for (int nt = 0; nt < 8; nt++) { tS0[nt] = 0.f; tS1[nt] = 0.f; }

    for (int tile = blockIdx.x; tile < NB; tile += gridDim.x) {
        const int rowBase = tile * 128;

        CP_WAIT0();
        __syncthreads();    // A visible

        // --- GEMM1: H1 = ReLU(A @ W1'^T + b1') ---
        float acc1[2][8][4];
#pragma unroll
        for (int rt = 0; rt < 2; rt++)
#pragma unroll
            for (int nt = 0; nt < 8; nt++)
#pragma unroll
                for (int j = 0; j < 4; j++) acc1[rt][nt][j] = 0.f;

#pragma unroll
        for (int kt = 0; kt < 8; kt++) {
            unsigned af0[4], af1[4], bf[4][4];
            ldsm4(af0, aAddr0 + kt * 32);
            ldsm4(af1, aAddr1 + kt * 32);
#pragma unroll
            for (int j = 0; j < 4; j++)
                ldsm4(bf[j], b1A + j * bStep + kt * 32);
#pragma unroll
            for (int nt = 0; nt < 8; nt++) {
                unsigned* bp = bf[nt >> 1];
                unsigned bb0 = bp[(nt & 1) * 2], bb1 = bp[(nt & 1) * 2 + 1];
                mma16(acc1[0][nt], af0[0], af0[1], af0[2], af0[3], bb0, bb1);
                mma16(acc1[1][nt], af1[0], af1[1], af1[2], af1[3], bb0, bb1);
            }
        }
        __syncthreads();

        // --- H1 -> sA (fp16) ---
#pragma unroll
        for (int rt = 0; rt < 2; rt++) {
            int r0 = rb + 16 * rt + gq;
#pragma unroll
            for (int nt = 0; nt < 8; nt++) {
                int c0 = cb + nt * 8 + q * 2;
                float o00 = fmaxf(acc1[rt][nt][0] + sB1[c0], 0.f);
                float o01 = fmaxf(acc1[rt][nt][1] + sB1[c0 + 1], 0.f);
                float o10 = fmaxf(acc1[rt][nt][2] + sB1[c0], 0.f);
                float o11 = fmaxf(acc1[rt][nt][3] + sB1[c0 + 1], 0.f);
                __half2 h0 = __floats2half2_rn(o00, o01);
                __half2 h1 = __floats2half2_rn(o10, o11);
                *(unsigned*)&sA[r0 * AS2 + c0] = *(unsigned*)&h0;
                *(unsigned*)&sA[(r0 + 8) * AS2 + c0] = *(unsigned*)&h1;
            }
        }
        __syncthreads();

        // --- GEMM2: H2 = ReLU(H1 @ W2^T + b2) ---
        float acc2[2][8][4];
#pragma unroll
        for (int rt = 0; rt < 2; rt++)
#pragma unroll
            for (int nt = 0; nt < 8; nt++)
#pragma unroll
                for (int j = 0; j < 4; j++) acc2[rt][nt][j] = 0.f;

#pragma unroll
        for (int kt = 0; kt < 8; kt++) {
            unsigned af0[4], af1[4], bf[4][4];
            ldsm4(af0, aAddr0 + kt * 32);
            ldsm4(af1, aAddr1 + kt * 32);
#pragma unroll
            for (int j = 0; j < 4; j++)
                ldsm4(bf[j], b2A + j * bStep + kt * 32);
#pragma unroll
            for (int nt = 0; nt < 8; nt++) {
                unsigned* bp = bf[nt >> 1];
                unsigned bb0 = bp[(nt & 1) * 2], bb1 = bp[(nt & 1) * 2 + 1];
                mma16(acc2[0][nt], af0[0], af0[1], af0[2], af0[3], bb0, bb1);
                mma16(acc2[1][nt], af1[0], af1[1], af1[2], af1[3], bb0, bb1);
            }
        }
        __syncthreads();    // all warps done reading sA (H1)

        // prefetch next tile's A into sA — overlaps the epilogue below
        int nxt = tile + gridDim.x;
        if (nxt < NB) {
            for (int idx = tid; idx < 4096; idx += 256) {
                int r = idx >> 5, c4 = idx & 31;
                cp_async8(aBase + (r * AS2 + c4 * 4) * 2,
                          &A2[(size_t)(nxt * 128 + r) * 32 + c4]);
            }
            CP_COMMIT();
        }

        // --- epilogue: write fp16 Xout, accumulate tap in fp32 regs ---
#pragma unroll
        for (int rt = 0; rt < 2; rt++) {
            int r0 = rowBase + rb + 16 * rt + gq;
            int r1 = r0 + 8;
            bool m0v = (r0 < NN), m1v = (r1 < NN);
#pragma unroll
            for (int nt = 0; nt < 8; nt++) {
                int c0 = cb + nt * 8 + q * 2;
                float o00 = m0v ? fmaxf(acc2[rt][nt][0] + sB2[c0], 0.f) : 0.f;
                float o01 = m0v ? fmaxf(acc2[rt][nt][1] + sB2[c0 + 1], 0.f) : 0.f;
                float o10 = m1v ? fmaxf(acc2[rt][nt][2] + sB2[c0], 0.f) : 0.f;
                float o11 = m1v ? fmaxf(acc2[rt][nt][3] + sB2[c0 + 1], 0.f) : 0.f;
                if (m0v) *(__half2*)&Xout[(size_t)r0 * 128 + c0] = __floats2half2_rn(o00, o01);
                if (m1v) *(__half2*)&Xout[(size_t)r1 * 128 + c0] = __floats2half2_rn(o10, o11);
                tS0[nt] += o00 + o10;
                tS1[nt] += o01 + o11;
            }
        }
    }

    // --- final tap reduction ---
#pragma unroll
    for (int nt = 0; nt < 8; nt++) {
        float t0 = tS0[nt], t1 = tS1[nt];
#pragma unroll
        for (int o = 16; o >= 4; o >>= 1) {
            t0 += __shfl_xor_sync(0xffffffffu, t0, o);
            t1 += __shfl_xor_sync(0xffffffffu, t1, o);
        }
        if (gq == 0) {
            int c0 = cb + nt * 8 + q * 2;
            atomicAdd(&sTap[c0], t0);
            atomicAdd(&sTap[c0 + 1], t1);
        }
    }
    __syncthreads();
    if (tid < 128) atomicAdd(&tap[tid], sTap[tid]);

    // --- fused readout on the last finishing block (final layer only) ---
    if (do_readout) {
        __shared__ int s_last;
        __threadfence();
        __syncthreads();
        if (tid == 0) {
            int prev = atomicAdd(&g_done, 1);
            s_last = (prev == (int)gridDim.x - 1);
        }
        __syncthreads();
        if (s_last && w < 10 && w < 8) { /* warps 0..7 only here; handle 10 rows below */ }
        if (s_last) {
            // 8 warps handle 10 outputs: warps 0..7 do rows 0..7; warp 0/1 redo rows 8/9
            for (int row = w; row < 10; row += 8) {
                float s = 0.f;
                for (int k = lane; k < 512; k += 32)
                    s += __ldcg(&g_tap[k]) * Wll[row * 512 + k];
#pragma unroll
                for (int o = 16; o; o >>= 1) s += __shfl_xor_sync(0xffffffffu, s, o);
                if (lane == 0) out[row] = s + bll[row];
            }
        }
    }
}

// ---------------- host ----------------
extern "C" void kernel_launch(void* const* d_in, const int* in_sizes, int n_in,
                              void* d_out, int out_size) {
    const float* x   = (const float*)d_in[0];
    const int*   ei  = (const int*)d_in[1];
    const float* W1_0 = (const float*)d_in[2];
    const float* b1_0 = (const float*)d_in[3];
    const float* g0   = (const float*)d_in[4];
    const float* be0  = (const float*)d_in[5];
    const float* m0   = (const float*)d_in[6];
    const float* v0   = (const float*)d_in[7];
    const float* W2_0 = (const float*)d_in[8];
    const float* b2_0 = (const float*)d_in[9];
    const float* W1s  = (const float*)d_in[10];
    const float* b1s  = (const float*)d_in[11];
    const float* gs   = (const float*)d_in[12];
    const float* bes  = (const float*)d_in[13];
    const float* ms   = (const float*)d_in[14];
    const float* vs   = (const float*)d_in[15];
    const float* W2s  = (const float*)d_in[16];
    const float* b2s  = (const float*)d_in[17];
    const float* Wll  = (const float*)d_in[18];
    const float* bll  = (const float*)d_in[19];
    float* out = (float*)d_out;

    cudaFuncSetAttribute(gin_layer, cudaFuncAttributeMaxDynamicSharedMemorySize, SMEM_BYTES);

    const int* esrc_in = ei;        // edge_index[0] = src
    const int* edst_in = ei + NE;   // edge_index[1] = dst

    void* dDeg; cudaGetSymbolAddress(&dDeg, g_deg);
    cudaMemsetAsync(dDeg, 0, NN * sizeof(int), 0);

    hist_k<<<(NE + 255) / 256, 256>>>(edst_in, x);
    scan_scatter_k<<<NSB, 256>>>(esrc_in, edst_in);

    __half* dh0; cudaGetSymbolAddress((void**)&dh0, g_h0);
    __half* dh1; cudaGetSymbolAddress((void**)&dh1, g_h1);
    __half* dh2; cudaGetSymbolAddress((void**)&dh2, g_h2);

    // 2 nodes per warp -> 25000 warps -> 3125 blocks of 256
    const int aggGrid = (NN / 2 * 32 + 255) / 256;

    const __half* ins[4]  = {dh0, dh1, dh2, dh1};
    __half*       outs[4] = {dh1, dh2, dh1, dh2};

    agg_k<<<aggGrid, 256>>>(ins[0]);
    gin_layer<<<PGRID, 256, SMEM_BYTES>>>(outs[0], 0, 0,
                                          W1_0, b1_0, g0, be0, m0, v0, W2_0, b2_0,
                                          Wll, bll, out);
    for (int i = 1; i < 4; i++) {
        int off = i - 1;
        agg_k<<<aggGrid, 256>>>(ins[i]);
        gin_layer<<<PGRID, 256, SMEM_BYTES>>>(outs[i], i * 128, (i == 3) ? 1 : 0,
                                              W1s + off * 16384, b1s + off * 128,
                                              gs + off * 128, bes + off * 128,
                                              ms + off * 128, vs + off * 128,
                                              W2s + off * 16384, b2s + off * 128,
                                              Wll, bll, out);
    }
}

// round 15
// speedup vs baseline: 1.0611x; 1.0611x over previous
#include <cuda_runtime.h>
#include <cuda_fp16.h>
#include <cstdint>

#define NN 50000
#define NE 600000
#define HIDD 128
#define AS2 136                      // padded row stride in halves: conflict-free
// dynamic smem: W1 | W2 | A0 | A1 (each 128*AS2 fp16) + stat floats
#define SMEM_BYTES (4 * 128 * AS2 * 2 + 2048)
#define NB ((NN + 127) / 128)        // 391 tiles
#define NSB ((NN + 255) / 256)       // scan blocks (196)
#define PGRID 148                    // persistent grid

#define ST_AGG (1 << 30)
#define ST_INC (2 << 30)
#define VALMASK 0x3FFFFFFF

// ---------------- device scratch (static, no runtime alloc) ----------------
__device__ __align__(16) __half g_h0[(size_t)NN * HIDD];   // fp16 x
__device__ __align__(16) __half g_h1[(size_t)NN * HIDD];   // fp16 activations
__device__ __align__(16) __half g_h2[(size_t)NN * HIDD];
// padded by 128 rows so tile prefetch past NN stays in-bounds
__device__ __align__(16) __half g_agg[(size_t)(NN + 128) * HIDD];
__device__ int   g_deg[NN];
__device__ int   g_rowptr[NN + 1];
__device__ int   g_cursor[NN];
__device__ __align__(16) int g_esrc[NE + 8];
__device__ int   g_lb[NSB];
__device__ int   g_done;
__device__ int   g_sync;
__device__ float g_tap[4 * HIDD];

// ---------------- helpers ----------------
__device__ __forceinline__ void mma16(float c[4], unsigned a0, unsigned a1, unsigned a2,
                                      unsigned a3, unsigned b0, unsigned b1) {
    asm volatile(
        "mma.sync.aligned.m16n8k16.row.col.f32.f16.f16.f32 "
        "{%0,%1,%2,%3},{%4,%5,%6,%7},{%8,%9},{%0,%1,%2,%3};"
        : "+f"(c[0]), "+f"(c[1]), "+f"(c[2]), "+f"(c[3])
        : "r"(a0), "r"(a1), "r"(a2), "r"(a3), "r"(b0), "r"(b1));
}

__device__ __forceinline__ void ldsm4(unsigned r[4], uint32_t addr) {
    asm volatile("ldmatrix.sync.aligned.m8n8.x4.shared.b16 {%0,%1,%2,%3}, [%4];"
                 : "=r"(r[0]), "=r"(r[1]), "=r"(r[2]), "=r"(r[3]) : "r"(addr));
}

__device__ __forceinline__ uint32_t smem_u32(const void* p) {
    uint32_t a;
    asm("{ .reg .u64 t; cvta.to.shared.u64 t, %1; cvt.u32.u64 %0, t; }" : "=r"(a) : "l"(p));
    return a;
}

__device__ __forceinline__ void cp_async8(uint32_t dst, const void* src) {
    asm volatile("cp.async.ca.shared.global [%0], [%1], 8;" :: "r"(dst), "l"(src));
}
#define CP_COMMIT() asm volatile("cp.async.commit_group;" ::: "memory")
#define CP_WAIT0()  asm volatile("cp.async.wait_group 0;" ::: "memory")
#define BAR_SYNC(id, n) asm volatile("bar.sync %0, %1;" :: "r"(id), "r"(n) : "memory")

// accumulate a single fp16 uint4 (8 halves) into 8 fp32
__device__ __forceinline__ void acc8(float f[8], uint4 v) {
    float2 a0 = __half22float2(*(__half2*)&v.x);
    float2 a1 = __half22float2(*(__half2*)&v.y);
    float2 a2 = __half22float2(*(__half2*)&v.z);
    float2 a3 = __half22float2(*(__half2*)&v.w);
    f[0] += a0.x; f[1] += a0.y; f[2] += a1.x; f[3] += a1.y;
    f[4] += a2.x; f[5] += a2.y; f[6] += a3.x; f[7] += a3.y;
}

// fp16 tree of 4 uint4s, then fp32 accumulate
__device__ __forceinline__ void tree4_8(float f[8], uint4 v0, uint4 v1, uint4 v2, uint4 v3) {
    __half2 s0 = __hadd2(__hadd2(*(__half2*)&v0.x, *(__half2*)&v1.x),
                         __hadd2(*(__half2*)&v2.x, *(__half2*)&v3.x));
    __half2 s1 = __hadd2(__hadd2(*(__half2*)&v0.y, *(__half2*)&v1.y),
                         __hadd2(*(__half2*)&v2.y, *(__half2*)&v3.y));
    __half2 s2 = __hadd2(__hadd2(*(__half2*)&v0.z, *(__half2*)&v1.z),
                         __hadd2(*(__half2*)&v2.z, *(__half2*)&v3.z));
    __half2 s3 = __hadd2(__hadd2(*(__half2*)&v0.w, *(__half2*)&v1.w),
                         __hadd2(*(__half2*)&v2.w, *(__half2*)&v3.w));
    float2 a0 = __half22float2(s0), a1 = __half22float2(s1);
    float2 a2 = __half22float2(s2), a3 = __half22float2(s3);
    f[0] += a0.x; f[1] += a0.y; f[2] += a1.x; f[3] += a1.y;
    f[4] += a2.x; f[5] += a2.y; f[6] += a3.x; f[7] += a3.y;
}

// ---------------- CSR build ----------------
__global__ void hist_k(const int* __restrict__ dst, const float* __restrict__ x) {
    int i = blockIdx.x * blockDim.x + threadIdx.x;
    if (i == 0) { g_done = 0; g_sync = 0; }
    if (i < NSB) g_lb[i] = 0;
    if (i < 4 * HIDD) g_tap[i] = 0.f;
    if (i < NE) atomicAdd(&g_deg[dst[i]], 1);
    const float2* x2 = (const float2*)x;
    __half2* h2 = (__half2*)g_h0;
    const int total = NN * HIDD / 2;
    for (int j = i; j < total; j += NE) {
        float2 v = x2[j];
        h2[j] = __floats2half2_rn(v.x, v.y);
    }
}

// fused: decoupled-lookback scan of g_deg -> grid barrier -> scatter edges
__global__ __launch_bounds__(256) void scan_scatter_k(const int* __restrict__ src,
                                                      const int* __restrict__ dst) {
    __shared__ int warpsum[8];
    __shared__ int s_prefix;
    const int b = blockIdx.x, t = threadIdx.x;
    const int lane = t & 31, wid = t >> 5;
    const int i = b * 256 + t;
    int d = (i < NN) ? g_deg[i] : 0;

    int v = d;
#pragma unroll
    for (int o = 1; o < 32; o <<= 1) {
        int u = __shfl_up_sync(0xffffffffu, v, o);
        if (lane >= o) v += u;
    }
    if (lane == 31) warpsum[wid] = v;
    __syncthreads();
    if (t < 8) {
        int wv = warpsum[t];
#pragma unroll
        for (int o = 1; o < 8; o <<= 1) {
            int u = __shfl_up_sync(0xffu, wv, o);
            if (t >= o) wv += u;
        }
        warpsum[t] = wv;
    }
    __syncthreads();
    const int incl = v + (wid ? warpsum[wid - 1] : 0);
    const int total = warpsum[7];

    if (t == 0) {
        if (b == 0) atomicExch(&g_lb[0], ST_INC | total);
        else        atomicExch(&g_lb[b], ST_AGG | total);
    }

    if (wid == 0) {
        int prefix = 0;
        if (b > 0) {
            int idx = b - 1;
            while (true) {
                int j = idx - lane;
                int w = (j >= 0) ? atomicAdd(&g_lb[j], 0) : (ST_INC | 0);
                if (!__all_sync(0xffffffffu, w != 0)) continue;
                unsigned incmask = __ballot_sync(0xffffffffu, (w & ST_INC) != 0);
                if (incmask) {
                    int first = __ffs(incmask) - 1;
                    int contrib = (lane <= first) ? (w & VALMASK) : 0;
#pragma unroll
                    for (int o = 16; o; o >>= 1) contrib += __shfl_xor_sync(0xffffffffu, contrib, o);
                    prefix += contrib;
                    break;
                } else {
                    int contrib = w & VALMASK;
#pragma unroll
                    for (int o = 16; o; o >>= 1) contrib += __shfl_xor_sync(0xffffffffu, contrib, o);
                    prefix += contrib;
                    idx -= 32;
                }
            }
            if (lane == 0) atomicExch(&g_lb[b], ST_INC | (prefix + total));
        }
        if (lane == 0) s_prefix = prefix;
    }
    __syncthreads();
    int rp = s_prefix + incl - d;
    if (i < NN) { g_rowptr[i] = rp; g_cursor[i] = rp; }
    if (i == NN - 1) g_rowptr[NN] = NE;

    // ---- grid barrier: all cursors published before any scatter ----
    __threadfence();
    __syncthreads();
    if (t == 0) {
        atomicAdd(&g_sync, 1);
        while (atomicAdd(&g_sync, 0) < NSB) { }
    }
    __syncthreads();

    // ---- scatter: grid-stride over edges ----
    for (int e = b * 256 + t; e < NE; e += NSB * 256) {
        int dd = dst[e];
        int pos = atomicAdd(&g_cursor[dd], 1);
        g_esrc[pos] = src[e];
    }
}

// ---------------- aggregation: 2 nodes per warp, uint4 rows, fp16 trees ----------------
__global__ __launch_bounds__(256) void agg_k(const __half* __restrict__ Xin) {
    const int warpId = (blockIdx.x * blockDim.x + threadIdx.x) >> 5;
    const int lane = threadIdx.x & 31;
    const int n = warpId * 2 + (lane >> 4);    // half-warp per node
    const int c = lane & 15;                   // 16 uint4 per 128-half row
    if (n >= NN) return;
    const uint4* X4 = (const uint4*)Xin;

    float f[8];
    {   // self term (eps=0 GIN)
        uint4 sv = X4[(size_t)n * 16 + c];
        float2 a0 = __half22float2(*(__half2*)&sv.x);
        float2 a1 = __half22float2(*(__half2*)&sv.y);
        float2 a2 = __half22float2(*(__half2*)&sv.z);
        float2 a3 = __half22float2(*(__half2*)&sv.w);
        f[0] = a0.x; f[1] = a0.y; f[2] = a1.x; f[3] = a1.y;
        f[4] = a2.x; f[5] = a2.y; f[6] = a3.x; f[7] = a3.y;
    }

    int e = g_rowptr[n];
    const int e1 = g_rowptr[n + 1];
    for (; e + 4 <= e1; e += 4) {
        int s0 = g_esrc[e],     s1 = g_esrc[e + 1];
        int s2 = g_esrc[e + 2], s3 = g_esrc[e + 3];
        uint4 v0 = X4[(size_t)s0 * 16 + c];
        uint4 v1 = X4[(size_t)s1 * 16 + c];
        uint4 v2 = X4[(size_t)s2 * 16 + c];
        uint4 v3 = X4[(size_t)s3 * 16 + c];
        tree4_8(f, v0, v1, v2, v3);
    }
    for (; e < e1; e++)
        acc8(f, X4[(size_t)g_esrc[e] * 16 + c]);

    __half2 o0 = __floats2half2_rn(f[0], f[1]);
    __half2 o1 = __floats2half2_rn(f[2], f[3]);
    __half2 o2 = __floats2half2_rn(f[4], f[5]);
    __half2 o3 = __floats2half2_rn(f[6], f[7]);
    uint4 st;
    st.x = *(unsigned*)&o0; st.y = *(unsigned*)&o1;
    st.z = *(unsigned*)&o2; st.w = *(unsigned*)&o3;
    ((uint4*)g_agg)[(size_t)n * 16 + c] = st;
}

// ---------------- persistent GIN MLP layer (R12 base + row-group named barriers) ----------------
__global__ __launch_bounds__(512, 1) void gin_layer(
    __half* __restrict__ Xout, int tap_off, int do_readout,
    const float* __restrict__ W1, const float* __restrict__ b1,
    const float* __restrict__ gam, const float* __restrict__ bet,
    const float* __restrict__ mu, const float* __restrict__ var,
    const float* __restrict__ W2, const float* __restrict__ b2,
    const float* __restrict__ Wll, const float* __restrict__ bll,
    float* __restrict__ out)
{
    extern __shared__ __half smh[];
    __half* sW1 = smh;                      // 128 x AS2 fp16 (BN-folded W1)
    __half* sW2 = smh + 128 * AS2;          // 128 x AS2 fp16 W2
    __half* sAb[2] = { smh + 2 * 128 * AS2, smh + 3 * 128 * AS2 };
    float* sB1    = (float*)(smh + 4 * 128 * AS2);
    float* sB2    = sB1 + 128;
    float* sTap   = sB2 + 128;
    float* sScale = sTap + 128;

    float* tap = g_tap + tap_off;

    const int tid = threadIdx.x;
    const int w = tid >> 5, lane = tid & 31;

    const uint2* A2 = (const uint2*)g_agg;
    const uint32_t aB[2] = { smem_u32(sAb[0]), smem_u32(sAb[1]) };

    // prefetch first tile into buffer 0 FIRST — overlaps the weight fold below
    {
        int tile = blockIdx.x;
        for (int idx = tid; idx < 4096; idx += 512) {
            int r = idx >> 5, c4 = idx & 31;
            cp_async8(aB[0] + (r * AS2 + c4 * 4) * 2,
                      &A2[(size_t)(tile * 128 + r) * 32 + c4]);
        }
        CP_COMMIT();
    }

    if (tid < 128) {
        float sc = gam[tid] * rsqrtf(var[tid] + 1e-5f);
        sScale[tid] = sc;
        sTap[tid] = 0.f;
        sB2[tid] = b2[tid];
        sB1[tid] = (b1[tid] - mu[tid]) * sc + bet[tid];
    }
    __syncthreads();   // sScale visible for weight fold

    // --- load both weight matrices once (float4 -> fp16) ---
    const float4* W14 = (const float4*)W1;
    const float4* W24 = (const float4*)W2;
    for (int idx = tid; idx < 4096; idx += 512) {
        int c = idx >> 5, k4 = (idx & 31) * 4;
        float s = sScale[c];
        float4 v1 = W14[idx];
        __half2 a0 = __floats2half2_rn(v1.x * s, v1.y * s);
        __half2 a1 = __floats2half2_rn(v1.z * s, v1.w * s);
        uint2 u1; u1.x = *(unsigned*)&a0; u1.y = *(unsigned*)&a1;
        *(uint2*)&sW1[c * AS2 + k4] = u1;
        float4 v2 = W24[idx];
        __half2 b0h = __floats2half2_rn(v2.x, v2.y);
        __half2 b1h = __floats2half2_rn(v2.z, v2.w);
        uint2 u2; u2.x = *(unsigned*)&b0h; u2.y = *(unsigned*)&b1h;
        *(uint2*)&sW2[c * AS2 + k4] = u2;
    }

    // warp tiling: 16 warps = 4 row-tiles x 4 col-strips
    const int wr = w & 3, wc = w >> 2;
    const int rb = wr * 32, cb = wc * 32;
    const int gq = lane >> 2, q = lane & 3;
    const int rbar = 1 + wr;    // named barrier per row-group (4 warps = 128 thr)

    // ldmatrix lane address components
    const int lg = lane >> 3, lr = lane & 7;
    const uint32_t aOff0 = ((rb + (lg & 1) * 8 + lr) * AS2 + ((lg >> 1) * 8)) * 2;
    const uint32_t aOff1 = aOff0 + 16 * AS2 * 2;
    const uint32_t bOffC = (((lg >> 1) * 8 + lr) * AS2 + ((lg & 1) * 8)) * 2;
    const uint32_t b1Addr0 = smem_u32(sW1) + (cb * AS2) * 2 + bOffC;
    const uint32_t b1Addr1 = b1Addr0 + 16 * AS2 * 2;
    const uint32_t b2Addr0 = smem_u32(sW2) + (cb * AS2) * 2 + bOffC;
    const uint32_t b2Addr1 = b2Addr0 + 16 * AS2 * 2;

    float tS0[4], tS1[4];
#pragma unroll
    for (int nt = 0; nt < 4; nt++) { tS0[nt] = 0.f; tS1[nt] = 0.f; }

    int bufi = 0;
    for (int tile = blockIdx.x; tile < NB; tile += gridDim.x, bufi ^= 1) {
        const int rowBase = tile * 128;
        __half* sA = sAb[bufi];
        const uint32_t aAddr0 = aB[bufi] + aOff0;
        const uint32_t aAddr1 = aB[bufi] + aOff1;

        CP_WAIT0();
        __syncthreads();    // A visible; all warps done with previous tile

        // prefetch next tile into the other buffer (overlaps both GEMMs)
        int nxt = tile + gridDim.x;
        if (nxt < NB) {
            uint32_t dstb = aB[bufi ^ 1];
            for (int idx = tid; idx < 4096; idx += 512) {
                int r = idx >> 5, c4 = idx & 31;
                cp_async8(dstb + (r * AS2 + c4 * 4) * 2,
                          &A2[(size_t)(nxt * 128 + r) * 32 + c4]);
            }
            CP_COMMIT();
        }

        // --- GEMM1: H1 = ReLU(A @ W1'^T + b1') ---
        float acc1[2][4][4];
#pragma unroll
        for (int rt = 0; rt < 2; rt++)
#pragma unroll
            for (int nt = 0; nt < 4; nt++)
#pragma unroll
                for (int j = 0; j < 4; j++) acc1[rt][nt][j] = 0.f;

#pragma unroll
        for (int kt = 0; kt < 8; kt++) {
            unsigned af0[4], af1[4], bfA[4], bfB[4];
            ldsm4(af0, aAddr0 + kt * 32);
            ldsm4(af1, aAddr1 + kt * 32);
            ldsm4(bfA, b1Addr0 + kt * 32);
            ldsm4(bfB, b1Addr1 + kt * 32);
            mma16(acc1[0][0], af0[0], af0[1], af0[2], af0[3], bfA[0], bfA[1]);
            mma16(acc1[0][1], af0[0], af0[1], af0[2], af0[3], bfA[2], bfA[3]);
            mma16(acc1[0][2], af0[0], af0[1], af0[2], af0[3], bfB[0], bfB[1]);
            mma16(acc1[0][3], af0[0], af0[1], af0[2], af0[3], bfB[2], bfB[3]);
            mma16(acc1[1][0], af1[0], af1[1], af1[2], af1[3], bfA[0], bfA[1]);
            mma16(acc1[1][1], af1[0], af1[1], af1[2], af1[3], bfA[2], bfA[3]);
            mma16(acc1[1][2], af1[0], af1[1], af1[2], af1[3], bfB[0], bfB[1]);
            mme_dummy:;
            mma16(acc1[1][3], af1[0], af1[1], af1[2], af1[3], bfB[2], bfB[3]);
        }
        // row-group barrier: the 4 warps sharing these A rows finished GEMM1
        BAR_SYNC(rbar, 128);

        // --- H1 -> sA (fp16), own rows/cols only ---
#pragma unroll
        for (int rt = 0; rt < 2; rt++) {
            int r0 = rb + 16 * rt + gq;
#pragma unroll
            for (int nt = 0; nt < 4; nt++) {
                int c0 = cb + nt * 8 + q * 2;
                float o00 = fmaxf(acc1[rt][nt][0] + sB1[c0], 0.f);
                float o01 = fmaxf(acc1[rt][nt][1] + sB1[c0 + 1], 0.f);
                float o10 = fmaxf(acc1[rt][nt][2] + sB1[c0], 0.f);
                float o11 = fmaxf(acc1[rt][nt][3] + sB1[c0 + 1], 0.f);
                __half2 h0 = __floats2half2_rn(o00, o01);
                __half2 h1 = __floats2half2_rn(o10, o11);
                *(unsigned*)&sA[r0 * AS2 + c0] = *(unsigned*)&h0;
                *(unsigned*)&sA[(r0 + 8) * AS2 + c0] = *(unsigned*)&h1;
            }
        }
        // row-group barrier: all 128 cols of this row-group's H1 written
        BAR_SYNC(rbar, 128);

        // --- GEMM2: H2 = ReLU(H1 @ W2^T + b2) ---
        float acc2[2][4][4];
#pragma unroll
        for (int rt = 0; rt < 2; rt++)
#pragma unroll
            for (int nt = 0; nt < 4; nt++)
#pragma unroll
                for (int j = 0; j < 4; j++) acc2[rt][nt][j] = 0.f;

#pragma unroll
        for (int kt = 0; kt < 8; kt++) {
            unsigned af0[4], af1[4], bfA[4], bfB[4];
            ldsm4(af0, aAddr0 + kt * 32);
            ldsm4(af1, aAddr1 + kt * 32);
            ldsm4(bfA, b2Addr0 + kt * 32);
            ldsm4(bfB, b2Addr1 + kt * 32);
            mma16(acc2[0][0], af0[0], af0[1], af0[2], af0[3], bfA[0], bfA[1]);
            mma16(acc2[0][1], af0[0], af0[1], af0[2], af0[3], bfA[2], bfA[3]);
            mma16(acc2[0][2], af0[0], af0[1], af0[2], af0[3], bfB[0], bfB[1]);
            mma16(acc2[0][3], af0[0], af0[1], af0[2], af0[3], bfB[2], bfB[3]);
            mma16(acc2[1][0], af1[0], af1[1], af1[2], af1[3], bfA[0], bfA[1]);
            mma16(acc2[1][1], af1[0], af1[1], af1[2], af1[3], bfA[2], bfA[3]);
            mma16(acc2[1][2], af1[0], af1[1], af1[2], af1[3], bfB[0], bfB[1]);
            mma16(acc2[1][3], af1[0], af1[1], af1[2], af1[3], bfB[2], bfB[3]);
        }

        // --- epilogue: write fp16 Xout, accumulate tap in fp32 regs ---
#pragma unroll
        for (int rt = 0; rt < 2; rt++) {
            int r0 = rowBase + rb + 16 * rt + gq;
            int r1 = r0 + 8;
            bool m0v = (r0 < NN), m1v = (r1 < NN);
#pragma unroll
            for (int nt = 0; nt < 4; nt++) {
                int c0 = cb + nt * 8 + q * 2;
                float o00 = m0v ? fmaxf(acc2[rt][nt][0] + sB2[c0], 0.f) : 0.f;
                float o01 = m0v ? fmaxf(acc2[rt][nt][1] + sB2[c0 + 1], 0.f) : 0.f;
                float o10 = m1v ? fmaxf(acc2[rt][nt][2] + sB2[c0], 0.f) : 0.f;
                float o11 = m1v ? fmaxf(acc2[rt][nt][3] + sB2[c0 + 1], 0.f) : 0.f;
                if (m0v) *(__half2*)&Xout[(size_t)r0 * 128 + c0] = __floats2half2_rn(o00, o01);
                if (m1v) *(__half2*)&Xout[(size_t)r1 * 128 + c0] = __floats2half2_rn(o10, o11);
                tS0[nt] += o00 + o10;
                tS1[nt] += o01 + o11;
            }
        }
        // no trailing sync: next loop-top CP_WAIT0 + __syncthreads covers it
    }

    // --- final tap reduction ---
#pragma unroll
    for (int nt = 0; nt < 4; nt++) {
        float t0 = tS0[nt], t1 = tS1[nt];
#pragma unroll
        for (int o = 16; o >= 4; o >>= 1) {
            t0 += __shfl_xor_sync(0xffffffffu, t0, o);
            t1 += __shfl_xor_sync(0xffffffffu, t1, o);
        }
        if (gq == 0) {
            int c0 = cb + nt * 8 + q * 2;
            atomicAdd(&sTap[c0], t0);
            atomicAdd(&sTap[c0 + 1], t1);
        }
    }
    __syncthreads();
    if (tid < 128) atomicAdd(&tap[tid], sTap[tid]);

    // --- fused readout on the last finishing block (final layer only) ---
    if (do_readout) {
        __shared__ int s_last;
        __threadfence();
        __syncthreads();
        if (tid == 0) {
            int prev = atomicAdd(&g_done, 1);
            s_last = (prev == (int)gridDim.x - 1);
        }
        __syncthreads();
        if (s_last && w < 10) {
            float s = 0.f;
            for (int k = lane; k < 512; k += 32)
                s += __ldcg(&g_tap[k]) * Wll[w * 512 + k];
#pragma unroll
            for (int o = 16; o; o >>= 1) s += __shfl_xor_sync(0xffffffffu, s, o);
            if (lane == 0) out[w] = s + bll[w];
        }
    }
}

// ---------------- host ----------------
extern "C" void kernel_launch(void* const* d_in, const int* in_sizes, int n_in,
                              void* d_out, int out_size) {
    const float* x   = (const float*)d_in[0];
    const int*   ei  = (const int*)d_in[1];
    const float* W1_0 = (const float*)d_in[2];
    const float* b1_0 = (const float*)d_in[3];
    const float* g0   = (const float*)d_in[4];
    const float* be0  = (const float*)d_in[5];
    const float* m0   = (const float*)d_in[6];
    const float* v0   = (const float*)d_in[7];
    const float* W2_0 = (const float*)d_in[8];
    const float* b2_0 = (const float*)d_in[9];
    const float* W1s  = (const float*)d_in[10];
    const float* b1s  = (const float*)d_in[11];
    const float* gs   = (const float*)d_in[12];
    const float* bes  = (const float*)d_in[13];
    const float* ms   = (const float*)d_in[14];
    const float* vs   = (const float*)d_in[15];
    const float* W2s  = (const float*)d_in[16];
    const float* b2s  = (const float*)d_in[17];
    const float* Wll  = (const float*)d_in[18];
    const float* bll  = (const float*)d_in[19];
    float* out = (float*)d_out;

    cudaFuncSetAttribute(gin_layer, cudaFuncAttributeMaxDynamicSharedMemorySize, SMEM_BYTES);

    const int* esrc_in = ei;        // edge_index[0] = src
    const int* edst_in = ei + NE;   // edge_index[1] = dst

    void* dDeg; cudaGetSymbolAddress(&dDeg, g_deg);
    cudaMemsetAsync(dDeg, 0, NN * sizeof(int), 0);

    hist_k<<<(NE + 255) / 256, 256>>>(edst_in, x);
    scan_scatter_k<<<NSB, 256>>>(esrc_in, edst_in);

    __half* dh0; cudaGetSymbolAddress((void**)&dh0, g_h0);
    __half* dh1; cudaGetSymbolAddress((void**)&dh1, g_h1);
    __half* dh2; cudaGetSymbolAddress((void**)&dh2, g_h2);

    // 2 nodes per warp -> 25000 warps -> 3125 blocks of 256
    const int aggGrid = (NN / 2 * 32 + 255) / 256;

    const __half* ins[4]  = {dh0, dh1, dh2, dh1};
    __half*       outs[4] = {dh1, dh2, dh1, dh2};

    agg_k<<<aggGrid, 256>>>(ins[0]);
    gin_layer<<<PGRID, 512, SMEM_BYTES>>>(outs[0], 0, 0,
                                          W1_0, b1_0, g0, be0, m0, v0, W2_0, b2_0,
                                          Wll, bll, out);
    for (int i = 1; i < 4; i++) {
        int off = i - 1;
        agg_k<<<aggGrid, 256>>>(ins[i]);
        gin_layer<<<PGRID, 512, SMEM_BYTES>>>(outs[i], i * 128, (i == 3) ? 1 : 0,
                                              W1s + off * 16384, b1s + off * 128,
                                              gs + off * 128, bes + off * 128,
                                              ms + off * 128, vs + off * 128,
                                              W2s + off * 16384, b2s + off * 128,
                                              Wll, bll, out);
    }
}